// round 8
// baseline (speedup 1.0000x reference)
#include <cuda_runtime.h>
#include <cuda_bf16.h>

// Problem:
//   decoder_states: (32, 512, 1024) f32   d_in[0]
//   encoder_states: (32,1024, 1024) f32   d_in[1]
//   step:           scalar int (unused)   d_in[2]
//   mlp_weight:     (1, 2048) f32         d_in[3]  [0:1024]=w_enc, [1024:2048]=w_dec
//   mlp_bias:       (1,) f32              d_in[4]
//   out[b,t,s] = dot(dec[b,t], w_dec) + dot(enc[b,s], w_enc) + bias

#define DIM        1024
#define BATCH      32
#define T_DEC      512
#define S_ENC      1024
#define N_DEC_ROWS (BATCH * T_DEC)   // 16384
#define N_ENC_ROWS (BATCH * S_ENC)   // 32768
#define ENC_ROWS_PER_WARP 4
#define RPB 16                       // decoder rows per block in fused kernel

// Scratch (allocation-free rule: __device__ global)
__device__ float g_enc_proj[N_ENC_ROWS];

__device__ __forceinline__ float dot4(const float4 a, const float4 w, float s) {
    s = fmaf(a.x, w.x, s);
    s = fmaf(a.y, w.y, s);
    s = fmaf(a.z, w.z, s);
    return fmaf(a.w, w.w, s);
}

// ---------------------------------------------------------------------------
// Kernel A: encoder projection. One warp per 4 rows.
// Weights loaded ONCE into registers (8 x float4), reused across all 4 rows:
// halves LDG count / L1 wavefronts vs R5 and raises useful load MLP to ~32.
// 32768 rows / 4 = 8192 warps -> 1024 blocks x 256 threads.
// ---------------------------------------------------------------------------
__global__ __launch_bounds__(256)
void enc_proj_kernel(const float4* __restrict__ enc4,
                     const float4* __restrict__ w4)   // w_enc = mlp_weight[0:1024]
{
    const int warp = (blockIdx.x * blockDim.x + threadIdx.x) >> 5;
    const int lane = threadIdx.x & 31;

    float4 W[8];
#pragma unroll
    for (int j = 0; j < 8; ++j) W[j] = __ldg(w4 + lane + 32 * j);

    const float4* __restrict__ src =
        enc4 + (size_t)warp * (ENC_ROWS_PER_WARP * DIM / 4);

    float s0 = 0.f, s1 = 0.f, s2 = 0.f, s3 = 0.f;
#pragma unroll
    for (int j = 0; j < 8; ++j) {
        const int idx = lane + 32 * j;
        const float4 a = __ldcs(src + idx);              // row 0
        const float4 b = __ldcs(src + 256 + idx);        // row 1
        const float4 c = __ldcs(src + 512 + idx);        // row 2
        const float4 d = __ldcs(src + 768 + idx);        // row 3
        s0 = dot4(a, W[j], s0);
        s1 = dot4(b, W[j], s1);
        s2 = dot4(c, W[j], s2);
        s3 = dot4(d, W[j], s3);
    }

#pragma unroll
    for (int off = 16; off > 0; off >>= 1) {
        s0 += __shfl_xor_sync(0xFFFFFFFFu, s0, off);
        s1 += __shfl_xor_sync(0xFFFFFFFFu, s1, off);
        s2 += __shfl_xor_sync(0xFFFFFFFFu, s2, off);
        s3 += __shfl_xor_sync(0xFFFFFFFFu, s3, off);
    }

    if (lane == 0) {
        float4 o; o.x = s0; o.y = s1; o.z = s2; o.w = s3;
        ((float4*)g_enc_proj)[warp] = o;   // rows warp*4 .. warp*4+3
    }
}

// ---------------------------------------------------------------------------
// Kernel B: fused decoder projection + broadcast write.
// Block = 256 threads handles (batch b, 16 consecutive t rows):
//   - stage enc_proj[b,:] (4 KB) in smem
//   - warp w computes dots for rows t0+2w, t0+2w+1 (weights in regs, 16 MLP)
//   - every thread writes 16 output rows: 16 independent STG.128
// Grid = 16384 / 16 = 1024 blocks.
// ---------------------------------------------------------------------------
__global__ __launch_bounds__(256)
void fused_dec_kernel(const float4* __restrict__ dec4,
                      const float4* __restrict__ w4,    // full mlp_weight
                      const float*  __restrict__ bias,
                      float4* __restrict__ out4)
{
    __shared__ float4 esm[S_ENC / 4];        // 4 KB: enc_proj row for batch b
    __shared__ float  dsm[RPB];

    const int blk  = blockIdx.x;             // 0..1023
    const int b    = blk >> 5;               // 32 chunks of 16 rows per batch
    const int t0   = (blk & 31) * RPB;
    const int tid  = threadIdx.x;
    const int w    = tid >> 5;
    const int lane = tid & 31;

    // stage enc_proj[b, :] -> smem (256 x float4 = 4 KB)
    esm[tid] = __ldg((const float4*)g_enc_proj + b * (S_ENC / 4) + tid);

    const float bi = __ldg(bias);

    const float4* __restrict__ wd = w4 + (DIM / 4);   // w_dec
    float4 W[8];
#pragma unroll
    for (int j = 0; j < 8; ++j) W[j] = __ldg(wd + lane + 32 * j);

    // warp w -> decoder rows t0 + 2w, t0 + 2w + 1
    const int row = (b << 9) + t0 + 2 * w;
    const float4* __restrict__ src = dec4 + (size_t)row * (DIM / 4);

    float s0 = 0.f, s1 = 0.f;
#pragma unroll
    for (int j = 0; j < 8; ++j) {
        const int idx = lane + 32 * j;
        const float4 a = __ldcs(src + idx);
        const float4 c = __ldcs(src + 256 + idx);
        s0 = dot4(a, W[j], s0);
        s1 = dot4(c, W[j], s1);
    }
#pragma unroll
    for (int off = 16; off > 0; off >>= 1) {
        s0 += __shfl_xor_sync(0xFFFFFFFFu, s0, off);
        s1 += __shfl_xor_sync(0xFFFFFFFFu, s1, off);
    }
    if (lane == 0) {
        dsm[2 * w]     = s0 + bi;
        dsm[2 * w + 1] = s1 + bi;
    }
    __syncthreads();

    // 16 independent streaming stores per thread
    const float4 e = esm[tid];
    float4* __restrict__ obase = out4 + (size_t)((b << 9) + t0) * (DIM / 4) + tid;
#pragma unroll
    for (int r = 0; r < RPB; ++r) {
        const float d = dsm[r];
        float4 o;
        o.x = d + e.x; o.y = d + e.y; o.z = d + e.z; o.w = d + e.w;
        __stcs(obase + (size_t)r * (DIM / 4), o);
    }
}

extern "C" void kernel_launch(void* const* d_in, const int* in_sizes, int n_in,
                              void* d_out, int out_size)
{
    const float4* dec4 = (const float4*)d_in[0];
    const float4* enc4 = (const float4*)d_in[1];
    // d_in[2] = step (unused)
    const float4* w4   = (const float4*)d_in[3];
    const float*  bias = (const float*)d_in[4];
    float4* out4 = (float4*)d_out;

    enc_proj_kernel<<<1024, 256>>>(enc4, w4);              // 8192 warps x 4 rows
    fused_dec_kernel<<<1024, 256>>>(dec4, w4, bias, out4); // 16 rows / block
}